// round 6
// baseline (speedup 1.0000x reference)
#include <cuda_runtime.h>

// Per-qubit Z-expval after the circuit: d_w(theta) = A_w cos(theta) + B_w sin(theta)
//   with A_w = cos(alpha_w)cos(beta_w), B_w = -sin(beta_w)  (Rz param is dead).
// Phase-folded: d_w = R_w * cos(theta - phi_w), R_w = |(A,B)|, phi_w = atan2(B,A).
// Entangler gives Z_k = prod_{j<=k} d_j, so with W'_k = W_k * prod_{j<=k} R_j the
// output is c0*(W0' + c1*(W1' + c2*(W2' + c3*W3'))), c_w = cos(theta_w - phi_w).
// -> 1 MUFU per pixel instead of 2.

__device__ __forceinline__ float patch_ev(float t0, float t1, float t2, float t3,
                                          float4 P, float4 Wf) {
    float c0 = __cosf(t0 - P.x);
    float c1 = __cosf(t1 - P.y);
    float c2 = __cosf(t2 - P.z);
    float c3 = __cosf(t3 - P.w);
    return c0 * fmaf(c1, fmaf(c2, fmaf(c3, Wf.w, Wf.z), Wf.y), Wf.x);
}

// One thread computes 4 patches: column-pair jj at patch-rows {i, i+7}.
// Threads: 8192 * 7 * 7 = 401408 = 1568 * 256 (exact, no bounds check).
__global__ void __launch_bounds__(256)
quanv_kernel(const float* __restrict__ x, const float* __restrict__ params,
             const float* __restrict__ W, float* __restrict__ out) {
    __shared__ __align__(16) float sqc[8];   // phi0..3, W'0..3

    if (threadIdx.x == 0) {
        float Rp = 1.0f;                     // cumulative product of R_w
        #pragma unroll
        for (int w = 0; w < 4; w++) {
            float a = params[3 * w + 0];
            float b = params[3 * w + 1];
            float A = cosf(a) * cosf(b);
            float B = -sinf(b);
            float R = sqrtf(fmaf(A, A, B * B));
            sqc[w] = atan2f(B, A);           // phi_w
            Rp *= R;
            sqc[4 + w] = W[w] * Rp;          // W'_w
        }
    }
    __syncthreads();

    int t  = blockIdx.x * 256 + threadIdx.x;
    int jj = t % 7;           // pair-of-patches column (j = 2jj, 2jj+1)
    int r  = t / 7;
    int i  = r % 7;           // patch row in [0,7); also handles i+7
    int b  = r / 7;           // image

    // x (B,1,28,28) f32: float4 row-chunk index = b*196 + i*14 + jj
    const float4* xr = reinterpret_cast<const float4*>(x);
    int o0 = b * 196 + i * 14 + jj;
    float4 r0 = xr[o0];         // row 2i
    float4 r1 = xr[o0 + 7];     // row 2i+1
    float4 r2 = xr[o0 + 98];    // row 2(i+7)
    float4 r3 = xr[o0 + 105];   // row 2(i+7)+1

    const float4* qc = reinterpret_cast<const float4*>(sqc);
    float4 Pv = qc[0], Wf = qc[1];

    float2 oA, oB;
    oA.x = patch_ev(r0.x, r0.y, r1.x, r1.y, Pv, Wf);
    oA.y = patch_ev(r0.z, r0.w, r1.z, r1.w, Pv, Wf);
    oB.x = patch_ev(r2.x, r2.y, r3.x, r3.y, Pv, Wf);
    oB.y = patch_ev(r2.z, r2.w, r3.z, r3.w, Pv, Wf);

    // out (B,196): float2 index b*98 + i*7 + jj; +49 for patch-row i+7
    float2* o2 = reinterpret_cast<float2*>(out);
    int q0 = b * 98 + i * 7 + jj;
    o2[q0]      = oA;
    o2[q0 + 49] = oB;
}

extern "C" void kernel_launch(void* const* d_in, const int* in_sizes, int n_in,
                              void* d_out, int out_size) {
    const float* x      = (const float*)d_in[0];
    const float* params = (const float*)d_in[1];
    const float* W      = (const float*)d_in[2];
    float* out          = (float*)d_out;

    quanv_kernel<<<1568, 256>>>(x, params, W, out);
}

// round 7
// speedup vs baseline: 1.2250x; 1.2250x over previous
#include <cuda_runtime.h>

// d_w(theta) = A_w cos(theta) + B_w sin(theta),  A_w = cos(alpha_w)cos(beta_w),
// B_w = -sin(beta_w)  (the Rz param is dead for Z expvals).
// Phase-folded: d_w = R_w cos(theta - phi_w). With W'_k = W_k * prod_{j<=k} R_j:
//   out = c0*(W0' + c1*(W1' + c2*(W2' + c3*W3'))),  c_w = __cosf(theta_w - phi_w).
// => 1 MUFU per pixel.

__device__ __forceinline__ float patch_ev(float t0, float t1, float t2, float t3,
                                          float4 P, float4 Wf) {
    float c0 = __cosf(t0 - P.x);
    float c1 = __cosf(t1 - P.y);
    float c2 = __cosf(t2 - P.z);
    float c3 = __cosf(t3 - P.w);
    return c0 * fmaf(c1, fmaf(c2, fmaf(c3, Wf.w, Wf.z), Wf.y), Wf.x);
}

// One thread computes 4 patches: column-pair jj at patch-rows {i, i+7}.
// Threads: 8192 * 7 * 7 = 401408 = 1568 * 256 (exact, no bounds check).
__global__ void __launch_bounds__(256)
quanv_kernel(const float* __restrict__ x, const float* __restrict__ params,
             const float* __restrict__ W, float* __restrict__ out) {
    __shared__ float sphi[4], sR[4], sW[4];

    int t  = blockIdx.x * 256 + threadIdx.x;
    int jj = t % 7;           // pair-of-patches column (j = 2jj, 2jj+1)
    int r  = t / 7;
    int i  = r % 7;           // patch row in [0,7); also handles i+7
    int b  = r / 7;           // image

    // Issue the big streaming loads FIRST so they are in flight while
    // threads 0-3 fetch params and run the (branchy) fold below.
    const float4* xr = reinterpret_cast<const float4*>(x);
    int o0 = b * 196 + i * 14 + jj;
    float4 r0 = xr[o0];         // row 2i
    float4 r1 = xr[o0 + 7];     // row 2i+1
    float4 r2 = xr[o0 + 98];    // row 2(i+7)
    float4 r3 = xr[o0 + 105];   // row 2(i+7)+1

    // Parallel per-qubit fold (no serial chain; param loads overlap x loads).
    if (threadIdx.x < 4) {
        int w = threadIdx.x;
        float a  = params[3 * w + 0];
        float bb = params[3 * w + 1];
        float A = cosf(a) * cosf(bb);
        float B = -sinf(bb);
        sR[w]   = sqrtf(fmaf(A, A, B * B));
        sphi[w] = atan2f(B, A);
        sW[w]   = W[w];
    }
    __syncthreads();

    // Cumulative weights computed per-thread from smem broadcasts (cheap,
    // avoids a second barrier / serial prefix in the prologue).
    float R0 = sR[0], R1 = sR[1], R2 = sR[2], R3 = sR[3];
    float p01 = R0 * R1, p012 = p01 * R2;
    float4 Wf = make_float4(sW[0] * R0, sW[1] * p01, sW[2] * p012, sW[3] * p012 * R3);
    float4 Pv = make_float4(sphi[0], sphi[1], sphi[2], sphi[3]);

    float2 oA, oB;
    oA.x = patch_ev(r0.x, r0.y, r1.x, r1.y, Pv, Wf);
    oA.y = patch_ev(r0.z, r0.w, r1.z, r1.w, Pv, Wf);
    oB.x = patch_ev(r2.x, r2.y, r3.x, r3.y, Pv, Wf);
    oB.y = patch_ev(r2.z, r2.w, r3.z, r3.w, Pv, Wf);

    // out (B,196): float2 index b*98 + i*7 + jj; +49 for patch-row i+7
    float2* o2 = reinterpret_cast<float2*>(out);
    int q0 = b * 98 + i * 7 + jj;
    o2[q0]      = oA;
    o2[q0 + 49] = oB;
}

extern "C" void kernel_launch(void* const* d_in, const int* in_sizes, int n_in,
                              void* d_out, int out_size) {
    const float* x      = (const float*)d_in[0];
    const float* params = (const float*)d_in[1];
    const float* W      = (const float*)d_in[2];
    float* out          = (float*)d_out;

    quanv_kernel<<<1568, 256>>>(x, params, W, out);
}